// round 5
// baseline (speedup 1.0000x reference)
#include <cuda_runtime.h>
#include <math.h>

// Problem constants
#define BB 8
#define CC1 256
#define CC2 256
#define HH 64
#define WW 64
#define HWS (HH*WW)           // 4096
#define KKT 9                 // K*K taps
#define RED (CC1*KKT)         // 2304 reduction length
#define PTILE 16              // pixels per deform block
#define CCH 32                // channels per chunk
#define NCH (CC1/CCH)         // 8 chunks
#define CKL (CCH*KKT)         // 288 ck per chunk

// Scratch (static device globals; allocation-free)
__device__ float g_xT[BB*HWS*CC1];     // NHWC x, 33.5 MB
__device__ float g_off[BB*HWS*18];     // per-pixel offsets (clipped)
__device__ float g_mask[BB*HWS*9];     // per-pixel sigmoid modulator
__device__ float g_wT[RED*CC2];        // reg_w transposed: [ck][oc]

// ---------------------------------------------------------------------------
// Kernel T: NCHW -> NHWC transpose of x
// ---------------------------------------------------------------------------
__global__ void __launch_bounds__(256) transpose_kernel(const float* __restrict__ x) {
    __shared__ float tile[32][33];
    int b  = blockIdx.z;
    int c0 = blockIdx.y * 32;
    int s0 = blockIdx.x * 32;
    int tx = threadIdx.x, ty = threadIdx.y;
#pragma unroll
    for (int i = 0; i < 32; i += 8)
        tile[ty + i][tx] = x[((b*CC1) + (c0 + ty + i)) * HWS + s0 + tx];
    __syncthreads();
#pragma unroll
    for (int i = 0; i < 32; i += 8)
        g_xT[(b*HWS + s0 + ty + i) * CC1 + c0 + tx] = tile[tx][ty + i];
}

// ---------------------------------------------------------------------------
// Kernel W: reg_w [oc][c][ky][kx] -> g_wT [ck][oc], ck = c*9 + k
// ---------------------------------------------------------------------------
__global__ void __launch_bounds__(256) wprep_kernel(const float* __restrict__ rw) {
    int ck = blockIdx.x;     // 0..2303
    int oc = threadIdx.x;    // 0..255
    g_wT[ck * CC2 + oc] = rw[oc * RED + ck];
}

// ---------------------------------------------------------------------------
// Kernel 1: fused offset(18ch, clip +-16) + modulator(9ch, sigmoid) conv 3x3
// block = (b, y-row), 256 threads: lane -> pixel pair, warp -> oc set {w, w+8, w+16, w+24}
// ---------------------------------------------------------------------------
__global__ void __launch_bounds__(256) conv1_kernel(const float* __restrict__ ow,
                                                    const float* __restrict__ ob,
                                                    const float* __restrict__ mw,
                                                    const float* __restrict__ mb) {
    int blk = blockIdx.x;
    int b = blk >> 6;
    int y = blk & 63;
    int t = threadIdx.x;
    int lane = t & 31, warp = t >> 5;
    int px0 = lane * 2;

    __shared__ float s_in[3 * 66 * 33];   // [row][px(-1..64)][c], c padded stride 33
    __shared__ float s_w[9 * 32 * 32];    // [k][c][oc padded to 32]

    float acc[2][4];
#pragma unroll
    for (int i = 0; i < 2; i++)
#pragma unroll
        for (int j = 0; j < 4; j++) acc[i][j] = 0.f;

    for (int cc = 0; cc < CC1; cc += 32) {
        // stage input rows y-1..y+1, channels cc..cc+31 (zero-padded borders)
        for (int i = t; i < 3 * 66 * 32; i += 256) {
            int c  = i & 31;
            int px = (i >> 5) % 66;
            int r  = i / (32 * 66);
            int yy = y - 1 + r;
            int xx = px - 1;
            float v = 0.f;
            if (yy >= 0 && yy < HH && xx >= 0 && xx < WW)
                v = g_xT[((b*HH + yy)*WW + xx) * CC1 + cc + c];
            s_in[(r * 66 + px) * 33 + c] = v;
        }
        // stage weight chunk for all 27 channels (pad oc to 32 with zeros)
        for (int i = t; i < 9 * 32 * 32; i += 256) {
            int oc = i & 31;
            int c  = (i >> 5) & 31;
            int k  = i >> 10;
            float v = 0.f;
            if (oc < 18)       v = ow[oc * RED + (cc + c) * 9 + k];
            else if (oc < 27)  v = mw[(oc - 18) * RED + (cc + c) * 9 + k];
            s_w[(k * 32 + c) * 32 + oc] = v;
        }
        __syncthreads();

#pragma unroll
        for (int k = 0; k < 9; ++k) {
            int r = k / 3, dxm = k % 3;
            const float* si = &s_in[(r * 66 + px0 + dxm) * 33];
            const float* sw = &s_w[k * 32 * 32];
#pragma unroll 4
            for (int c = 0; c < 32; ++c) {
                float v0 = si[c];
                float v1 = si[33 + c];
#pragma unroll
                for (int j = 0; j < 4; ++j) {
                    float wv = sw[c * 32 + warp + 8 * j];
                    acc[0][j] += v0 * wv;
                    acc[1][j] += v1 * wv;
                }
            }
        }
        __syncthreads();
    }

    // epilogue: bias + clip / sigmoid, scatter to per-pixel layout
#pragma unroll
    for (int pi = 0; pi < 2; ++pi) {
        int x = px0 + pi;
        int pix = (b*HH + y)*WW + x;
#pragma unroll
        for (int j = 0; j < 4; ++j) {
            int oc = warp + 8 * j;
            if (oc >= 27) continue;
            float v = acc[pi][j];
            if (oc < 18) {
                v += ob[oc];
                v = fminf(fmaxf(v, -16.0f), 16.0f);
                g_off[pix * 18 + oc] = v;
            } else {
                v += mb[oc - 18];
                g_mask[pix * 9 + (oc - 18)] = 1.0f / (1.0f + expf(-v));
            }
        }
    }
}

// ---------------------------------------------------------------------------
// Kernel 2: deformable gather + GEMM.
// block = (b, 16-pixel tile in one row). 256 threads.
//   coord phase: 144 threads precompute 4 corner indices + (bilinear*mask*valid) weights
//   per c-chunk: sample val[288][16] into smem, then GEMM: thread=oc, f32x2-packed px pairs
// ---------------------------------------------------------------------------
#define FMA2(d, a, b2) asm("fma.rn.f32x2 %0, %1, %2, %0;" : "+l"(d) : "l"(a), "l"(b2))

__global__ void __launch_bounds__(256, 2) deform_kernel(float* __restrict__ out) {
    int blk  = blockIdx.x;          // 0..2047
    int b    = blk >> 8;
    int tile = blk & 255;
    int y    = tile >> 2;
    int x0   = (tile & 3) * PTILE;

    int t = threadIdx.x;
    int lane = t & 31, warp = t >> 5;

    __shared__ int4   s_idx[KKT * PTILE];    // 144 corner index quads
    __shared__ float4 s_wt [KKT * PTILE];    // 144 corner weight quads
    __shared__ __align__(16) float s_val[CKL * PTILE];  // [ck_local][px]

    if (t < KKT * PTILE) {
        int k  = t >> 4;
        int px = t & 15;
        int x  = x0 + px;
        int pix = (b*HH + y)*WW + x;
        float dy = g_off[pix * 18 + 2 * k];
        float dx = g_off[pix * 18 + 2 * k + 1];
        float m  = g_mask[pix * 9 + k];
        float py  = dy + (float)(k / 3) + (float)(y - 1);
        float pxf = dx + (float)(k % 3) + (float)(x - 1);
        float y0f = floorf(py), x0f = floorf(pxf);
        float ly = py - y0f, lx = pxf - x0f;
        float hy = 1.f - ly, hx = 1.f - lx;
        int yi0 = (int)y0f, xi0 = (int)x0f;
        int yi1 = yi0 + 1, xi1 = xi0 + 1;
        bool vy0 = ((unsigned)yi0 < (unsigned)HH), vy1 = ((unsigned)yi1 < (unsigned)HH);
        bool vx0 = ((unsigned)xi0 < (unsigned)WW), vx1 = ((unsigned)xi1 < (unsigned)WW);
        int cy0 = min(max(yi0, 0), HH - 1), cy1 = min(max(yi1, 0), HH - 1);
        int cx0 = min(max(xi0, 0), WW - 1), cx1 = min(max(xi1, 0), WW - 1);
        int base = b * HWS;
        s_idx[t] = make_int4((base + cy0 * WW + cx0) * CC1,
                             (base + cy0 * WW + cx1) * CC1,
                             (base + cy1 * WW + cx0) * CC1,
                             (base + cy1 * WW + cx1) * CC1);
        s_wt[t] = make_float4(hy * hx * m * ((vy0 && vx0) ? 1.f : 0.f),
                              hy * lx * m * ((vy0 && vx1) ? 1.f : 0.f),
                              ly * hx * m * ((vy1 && vx0) ? 1.f : 0.f),
                              ly * lx * m * ((vy1 && vx1) ? 1.f : 0.f));
    }
    __syncthreads();

    unsigned long long acc[8];
#pragma unroll
    for (int i = 0; i < 8; ++i) acc[i] = 0ull;

    int oc = t;
    const float* __restrict__ xT = g_xT;

    for (int cc = 0; cc < NCH; ++cc) {
        int cbase = cc * CCH + lane;
        // ---- sampling: lane = channel, warps sweep (k, px) pairs ----
        for (int p = warp; p < KKT * PTILE; p += 8) {
            int k  = p >> 4;
            int px = p & 15;
            int4   id = s_idx[p];
            float4 w  = s_wt[p];
            float v = w.x * __ldg(&xT[id.x + cbase])
                    + w.y * __ldg(&xT[id.y + cbase])
                    + w.z * __ldg(&xT[id.z + cbase])
                    + w.w * __ldg(&xT[id.w + cbase]);
            s_val[(lane * KKT + k) * PTILE + px] = v;
        }
        __syncthreads();

        // ---- GEMM: thread = oc, 16 px as 8 packed f32x2 accumulators ----
        const float* __restrict__ wp = g_wT + (cc * CKL) * CC2 + oc;
#pragma unroll 4
        for (int ck = 0; ck < CKL; ++ck) {
            float wv = __ldg(wp + ck * CC2);
            unsigned wu = __float_as_uint(wv);
            unsigned long long w2;
            asm("mov.b64 %0, {%1, %1};" : "=l"(w2) : "r"(wu));
            const ulonglong2* vp = reinterpret_cast<const ulonglong2*>(&s_val[ck * PTILE]);
            ulonglong2 vA = vp[0];
            ulonglong2 vB = vp[1];
            FMA2(acc[0], vA.x, w2);
            FMA2(acc[1], vA.y, w2);
            FMA2(acc[2], vB.x, w2);
            FMA2(acc[3], vB.y, w2);
            vA = vp[2];
            vB = vp[3];
            FMA2(acc[4], vA.x, w2);
            FMA2(acc[5], vA.y, w2);
            FMA2(acc[6], vB.x, w2);
            FMA2(acc[7], vB.y, w2);
        }
        __syncthreads();
    }

    // ---- write NCHW output: 4x float4 per thread ----
    float* op = out + ((b * CC2 + oc) * HH + y) * WW + x0;
#pragma unroll
    for (int i = 0; i < 4; ++i) {
        unsigned long long a0 = acc[2 * i], a1 = acc[2 * i + 1];
        float4 o4;
        o4.x = __uint_as_float((unsigned)(a0 & 0xffffffffull));
        o4.y = __uint_as_float((unsigned)(a0 >> 32));
        o4.z = __uint_as_float((unsigned)(a1 & 0xffffffffull));
        o4.w = __uint_as_float((unsigned)(a1 >> 32));
        reinterpret_cast<float4*>(op)[i] = o4;
    }
}

// ---------------------------------------------------------------------------
extern "C" void kernel_launch(void* const* d_in, const int* in_sizes, int n_in,
                              void* d_out, int out_size) {
    const float* x        = (const float*)d_in[0];
    const float* offset_w = (const float*)d_in[1];
    const float* offset_b = (const float*)d_in[2];
    const float* mod_w    = (const float*)d_in[3];
    const float* mod_b    = (const float*)d_in[4];
    const float* reg_w    = (const float*)d_in[5];
    float* out = (float*)d_out;

    dim3 tb(32, 8);
    dim3 tg(HWS / 32, CC1 / 32, BB);
    transpose_kernel<<<tg, tb>>>(x);
    wprep_kernel<<<RED, 256>>>(reg_w);
    conv1_kernel<<<BB * HH, 256>>>(offset_w, offset_b, mod_w, mod_b);
    deform_kernel<<<BB * (HWS / PTILE), 256>>>(out);
}

// round 7
// speedup vs baseline: 1.2202x; 1.2202x over previous
#include <cuda_runtime.h>
#include <math.h>

// Problem constants
#define BB 8
#define CC1 256
#define CC2 256
#define HH 64
#define WW 64
#define HWS (HH*WW)           // 4096
#define KKT 9                 // K*K taps
#define RED (CC1*KKT)         // 2304 reduction length
#define CCH 32                // channels per chunk
#define NCH (CC1/CCH)         // 8 chunks
#define CKL (CCH*KKT)         // 288 ck rows per chunk

// Scratch (static device globals; allocation-free)
__device__ float g_xT[BB*HWS*CC1];     // NHWC x, 33.5 MB
__device__ float g_off[BB*HWS*18];     // per-pixel offsets (clipped)
__device__ float g_mask[BB*HWS*9];     // per-pixel sigmoid modulator
__device__ float g_wT[RED*CC2];        // reg_w transposed: [ck][oc]

// ---------------------------------------------------------------------------
// Kernel T: NCHW -> NHWC transpose of x
// ---------------------------------------------------------------------------
__global__ void __launch_bounds__(256) transpose_kernel(const float* __restrict__ x) {
    __shared__ float tile[32][33];
    int b  = blockIdx.z;
    int c0 = blockIdx.y * 32;
    int s0 = blockIdx.x * 32;
    int tx = threadIdx.x, ty = threadIdx.y;
#pragma unroll
    for (int i = 0; i < 32; i += 8)
        tile[ty + i][tx] = x[((b*CC1) + (c0 + ty + i)) * HWS + s0 + tx];
    __syncthreads();
#pragma unroll
    for (int i = 0; i < 32; i += 8)
        g_xT[(b*HWS + s0 + ty + i) * CC1 + c0 + tx] = tile[tx][ty + i];
}

// ---------------------------------------------------------------------------
// Kernel W: reg_w [oc][c][ky][kx] -> g_wT [ck][oc], ck = c*9 + k
// ---------------------------------------------------------------------------
__global__ void __launch_bounds__(256) wprep_kernel(const float* __restrict__ rw) {
    int ck = blockIdx.x;     // 0..2303
    int oc = threadIdx.x;    // 0..255
    g_wT[ck * CC2 + oc] = rw[oc * RED + ck];
}

// ---------------------------------------------------------------------------
// Kernel 1: fused offset(18ch, clip +-16) + modulator(9ch, sigmoid) conv 3x3
// ---------------------------------------------------------------------------
__global__ void __launch_bounds__(256) conv1_kernel(const float* __restrict__ ow,
                                                    const float* __restrict__ ob,
                                                    const float* __restrict__ mw,
                                                    const float* __restrict__ mb) {
    int blk = blockIdx.x;
    int b = blk >> 6;
    int y = blk & 63;
    int t = threadIdx.x;
    int lane = t & 31, warp = t >> 5;
    int px0 = lane * 2;

    __shared__ float s_in[3 * 66 * 33];   // [row][px(-1..64)][c], c padded stride 33
    __shared__ float s_w[9 * 32 * 32];    // [k][c][oc padded to 32]

    float acc[2][4];
#pragma unroll
    for (int i = 0; i < 2; i++)
#pragma unroll
        for (int j = 0; j < 4; j++) acc[i][j] = 0.f;

    for (int cc = 0; cc < CC1; cc += 32) {
        for (int i = t; i < 3 * 66 * 32; i += 256) {
            int c  = i & 31;
            int px = (i >> 5) % 66;
            int r  = i / (32 * 66);
            int yy = y - 1 + r;
            int xx = px - 1;
            float v = 0.f;
            if (yy >= 0 && yy < HH && xx >= 0 && xx < WW)
                v = g_xT[((b*HH + yy)*WW + xx) * CC1 + cc + c];
            s_in[(r * 66 + px) * 33 + c] = v;
        }
        for (int i = t; i < 9 * 32 * 32; i += 256) {
            int oc = i & 31;
            int c  = (i >> 5) & 31;
            int k  = i >> 10;
            float v = 0.f;
            if (oc < 18)       v = ow[oc * RED + (cc + c) * 9 + k];
            else if (oc < 27)  v = mw[(oc - 18) * RED + (cc + c) * 9 + k];
            s_w[(k * 32 + c) * 32 + oc] = v;
        }
        __syncthreads();

#pragma unroll
        for (int k = 0; k < 9; ++k) {
            int r = k / 3, dxm = k % 3;
            const float* si = &s_in[(r * 66 + px0 + dxm) * 33];
            const float* sw = &s_w[k * 32 * 32];
#pragma unroll 4
            for (int c = 0; c < 32; ++c) {
                float v0 = si[c];
                float v1 = si[33 + c];
#pragma unroll
                for (int j = 0; j < 4; ++j) {
                    float wv = sw[c * 32 + warp + 8 * j];
                    acc[0][j] += v0 * wv;
                    acc[1][j] += v1 * wv;
                }
            }
        }
        __syncthreads();
    }

#pragma unroll
    for (int pi = 0; pi < 2; ++pi) {
        int x = px0 + pi;
        int pix = (b*HH + y)*WW + x;
#pragma unroll
        for (int j = 0; j < 4; ++j) {
            int oc = warp + 8 * j;
            if (oc >= 27) continue;
            float v = acc[pi][j];
            if (oc < 18) {
                v += ob[oc];
                v = fminf(fmaxf(v, -16.0f), 16.0f);
                g_off[pix * 18 + oc] = v;
            } else {
                v += mb[oc - 18];
                g_mask[pix * 9 + (oc - 18)] = 1.0f / (1.0f + expf(-v));
            }
        }
    }
}

// ---------------------------------------------------------------------------
// Kernel 2: deformable gather + register-tiled GEMM.
// Block = (b, y): full 64-px row x 256 oc. 256 threads.
//   thread t: ocg = t&63 (4 oc), pxg = t>>6 (16 px) -> 4x16 register tile.
// Per chunk (32 channels):
//   sampler: lane = channel, tasks = (k, px-quad); writes float4 with
//            XOR(ck&15) slot swizzle -> <=2-way STS conflicts, coalesced gathers.
//   GEMM: per ck: 1 LDG.128 (4 weights) + 4 broadcast LDS.128 (16 px) + 32 FFMA2.
// ---------------------------------------------------------------------------
#define FMA2(d, a, b2) asm("fma.rn.f32x2 %0, %1, %2, %0;" : "+l"(d) : "l"(a), "l"(b2))

extern __shared__ float smem_dyn[];

__global__ void __launch_bounds__(256, 2) deform_kernel(float* __restrict__ out) {
    int blk = blockIdx.x;          // 0..511
    int b   = blk >> 6;
    int y   = blk & 63;

    float*  s_val = smem_dyn;                          // [288][64] floats, 72 KB
    int4*   s_idx = (int4*)(smem_dyn + CKL * WW);      // [576]
    float4* s_wt  = (float4*)((char*)s_idx + KKT * WW * sizeof(int4)); // [576]

    int t = threadIdx.x;
    int lane = t & 31, warp = t >> 5;

    // ---- coord phase: 576 entries (k, px) across full row ----
    for (int i = t; i < KKT * WW; i += 256) {
        int k  = i >> 6;      // 0..8
        int x  = i & 63;      // px in row
        int pix = (b*HH + y)*WW + x;
        float dy = g_off[pix * 18 + 2 * k];
        float dx = g_off[pix * 18 + 2 * k + 1];
        float m  = g_mask[pix * 9 + k];
        float py  = dy + (float)(k / 3) + (float)(y - 1);
        float pxf = dx + (float)(k % 3) + (float)(x - 1);
        float y0f = floorf(py), x0f = floorf(pxf);
        float ly = py - y0f, lx = pxf - x0f;
        float hy = 1.f - ly, hx = 1.f - lx;
        int yi0 = (int)y0f, xi0 = (int)x0f;
        int yi1 = yi0 + 1, xi1 = xi0 + 1;
        bool vy0 = ((unsigned)yi0 < (unsigned)HH), vy1 = ((unsigned)yi1 < (unsigned)HH);
        bool vx0 = ((unsigned)xi0 < (unsigned)WW), vx1 = ((unsigned)xi1 < (unsigned)WW);
        int cy0 = min(max(yi0, 0), HH - 1), cy1 = min(max(yi1, 0), HH - 1);
        int cx0 = min(max(xi0, 0), WW - 1), cx1 = min(max(xi1, 0), WW - 1);
        int base = b * HWS;
        s_idx[i] = make_int4((base + cy0 * WW + cx0) * CC1,
                             (base + cy0 * WW + cx1) * CC1,
                             (base + cy1 * WW + cx0) * CC1,
                             (base + cy1 * WW + cx1) * CC1);
        s_wt[i] = make_float4(hy * hx * m * ((vy0 && vx0) ? 1.f : 0.f),
                              hy * lx * m * ((vy0 && vx1) ? 1.f : 0.f),
                              ly * hx * m * ((vy1 && vx0) ? 1.f : 0.f),
                              ly * lx * m * ((vy1 && vx1) ? 1.f : 0.f));
    }
    __syncthreads();

    int ocg = t & 63;     // 4 consecutive oc starting at ocg*4
    int pxg = t >> 6;     // 16 px starting at pxg*16

    unsigned long long acc[4][8];
#pragma unroll
    for (int o = 0; o < 4; ++o)
#pragma unroll
        for (int i = 0; i < 8; ++i) acc[o][i] = 0ull;

    const float* __restrict__ xT = g_xT;
    const float4* __restrict__ wt4 = (const float4*)g_wT;  // [ck][64 float4]
    const ulonglong2* __restrict__ sv2 = (const ulonglong2*)s_val;
    float4* sv4 = (float4*)s_val;

    for (int cc = 0; cc < NCH; ++cc) {
        // ---- sampling: 144 tasks (k, px-quad), lane = channel ----
        int cb = cc * CCH + lane;
        for (int p = warp; p < KKT * 16; p += 8) {
            int k   = p >> 4;
            int px4 = p & 15;
            float vr[4];
#pragma unroll
            for (int j = 0; j < 4; ++j) {
                int e = k * WW + px4 * 4 + j;
                int4   id = s_idx[e];
                float4 w  = s_wt[e];
                vr[j] = w.x * __ldg(&xT[id.x + cb])
                      + w.y * __ldg(&xT[id.y + cb])
                      + w.z * __ldg(&xT[id.z + cb])
                      + w.w * __ldg(&xT[id.w + cb]);
            }
            int ckl = lane * KKT + k;                     // c*9 + k
            sv4[ckl * 16 + (px4 ^ (ckl & 15))] = make_float4(vr[0], vr[1], vr[2], vr[3]);
        }
        __syncthreads();

        // ---- GEMM: thread = 4 oc x 16 px ----
        const float4* __restrict__ wrow = wt4 + (size_t)(cc * CKL) * 64 + ocg;
        for (int ckl = 0; ckl < CKL; ++ckl) {
            float4 w = __ldg(wrow + ckl * 64);
            int swz = ckl & 15;
            ulonglong2 v[4];
#pragma unroll
            for (int i = 0; i < 4; ++i)
                v[i] = sv2[ckl * 16 + ((pxg * 4 + i) ^ swz)];
            unsigned long long w2;
#define DOOC(o, comp)                                                      \
            { unsigned wu = __float_as_uint(comp);                         \
              asm("mov.b64 %0, {%1, %1};" : "=l"(w2) : "r"(wu));           \
              FMA2(acc[o][0], v[0].x, w2); FMA2(acc[o][1], v[0].y, w2);    \
              FMA2(acc[o][2], v[1].x, w2); FMA2(acc[o][3], v[1].y, w2);    \
              FMA2(acc[o][4], v[2].x, w2); FMA2(acc[o][5], v[2].y, w2);    \
              FMA2(acc[o][6], v[3].x, w2); FMA2(acc[o][7], v[3].y, w2); }
            DOOC(0, w.x)
            DOOC(1, w.y)
            DOOC(2, w.z)
            DOOC(3, w.w)
#undef DOOC
        }
        __syncthreads();
    }

    // ---- write NCHW output: 4 oc x 16 px per thread ----
    int x0 = pxg * 16;
#pragma unroll
    for (int o = 0; o < 4; ++o) {
        int oc = ocg * 4 + o;
        float* op = out + (((size_t)(b * CC2 + oc) * HH + y) * WW + x0);
#pragma unroll
        for (int i = 0; i < 4; ++i) {
            unsigned long long a0 = acc[o][2 * i], a1 = acc[o][2 * i + 1];
            float4 o4;
            o4.x = __uint_as_float((unsigned)(a0 & 0xffffffffull));
            o4.y = __uint_as_float((unsigned)(a0 >> 32));
            o4.z = __uint_as_float((unsigned)(a1 & 0xffffffffull));
            o4.w = __uint_as_float((unsigned)(a1 >> 32));
            reinterpret_cast<float4*>(op)[i] = o4;
        }
    }
}

// ---------------------------------------------------------------------------
extern "C" void kernel_launch(void* const* d_in, const int* in_sizes, int n_in,
                              void* d_out, int out_size) {
    const float* x        = (const float*)d_in[0];
    const float* offset_w = (const float*)d_in[1];
    const float* offset_b = (const float*)d_in[2];
    const float* mod_w    = (const float*)d_in[3];
    const float* mod_b    = (const float*)d_in[4];
    const float* reg_w    = (const float*)d_in[5];
    float* out = (float*)d_out;

    const int DEFORM_SMEM = CKL * WW * sizeof(float)            // s_val 72 KB
                          + KKT * WW * sizeof(int4)             // s_idx 9 KB
                          + KKT * WW * sizeof(float4);          // s_wt  9 KB
    cudaFuncSetAttribute(deform_kernel, cudaFuncAttributeMaxDynamicSharedMemorySize,
                         DEFORM_SMEM);

    dim3 tb(32, 8);
    dim3 tg(HWS / 32, CC1 / 32, BB);
    transpose_kernel<<<tg, tb>>>(x);
    wprep_kernel<<<RED, 256>>>(reg_w);
    conv1_kernel<<<BB * HH, 256>>>(offset_w, offset_b, mod_w, mod_b);
    deform_kernel<<<BB * HH, 256, DEFORM_SMEM>>>(out);
}

// round 10
// speedup vs baseline: 1.4005x; 1.1477x over previous
#include <cuda_runtime.h>
#include <math.h>

// Problem constants
#define BB 8
#define CC1 256
#define CC2 256
#define HH 64
#define WW 64
#define HWS (HH*WW)           // 4096
#define KKT 9                 // K*K taps
#define RED (CC1*KKT)         // 2304 reduction length
#define CCH 32                // channels per chunk
#define NCH (CC1/CCH)         // 8 chunks
#define CKL (CCH*KKT)         // 288 ck rows per chunk
#define PXB 32                // pixels per deform block (half row)

// Scratch (static device globals; allocation-free)
__device__ float g_xT[BB*HWS*CC1];     // NHWC x, 33.5 MB
__device__ float g_off[BB*HWS*18];     // per-pixel offsets (clipped)
__device__ float g_mask[BB*HWS*9];     // per-pixel sigmoid modulator
__device__ float g_wT[RED*CC2];        // reg_w transposed: [ck][oc]

// ---------------------------------------------------------------------------
// Kernel T: NCHW -> NHWC transpose of x
// ---------------------------------------------------------------------------
__global__ void __launch_bounds__(256) transpose_kernel(const float* __restrict__ x) {
    __shared__ float tile[32][33];
    int b  = blockIdx.z;
    int c0 = blockIdx.y * 32;
    int s0 = blockIdx.x * 32;
    int tx = threadIdx.x, ty = threadIdx.y;
#pragma unroll
    for (int i = 0; i < 32; i += 8)
        tile[ty + i][tx] = x[((b*CC1) + (c0 + ty + i)) * HWS + s0 + tx];
    __syncthreads();
#pragma unroll
    for (int i = 0; i < 32; i += 8)
        g_xT[(b*HWS + s0 + ty + i) * CC1 + c0 + tx] = tile[tx][ty + i];
}

// ---------------------------------------------------------------------------
// Kernel W: reg_w [oc][c][ky][kx] -> g_wT [ck][oc], ck = c*9 + k
// ---------------------------------------------------------------------------
__global__ void __launch_bounds__(256) wprep_kernel(const float* __restrict__ rw) {
    int ck = blockIdx.x;     // 0..2303
    int oc = threadIdx.x;    // 0..255
    g_wT[ck * CC2 + oc] = rw[oc * RED + ck];
}

// ---------------------------------------------------------------------------
// Kernel 1: fused offset(18ch, clip +-16) + modulator(9ch, sigmoid) conv 3x3
// ---------------------------------------------------------------------------
__global__ void __launch_bounds__(256) conv1_kernel(const float* __restrict__ ow,
                                                    const float* __restrict__ ob,
                                                    const float* __restrict__ mw,
                                                    const float* __restrict__ mb) {
    int blk = blockIdx.x;
    int b = blk >> 6;
    int y = blk & 63;
    int t = threadIdx.x;
    int lane = t & 31, warp = t >> 5;
    int px0 = lane * 2;

    __shared__ float s_in[3 * 66 * 33];   // [row][px(-1..64)][c], c padded stride 33
    __shared__ float s_w[9 * 32 * 32];    // [k][c][oc padded to 32]

    float acc[2][4];
#pragma unroll
    for (int i = 0; i < 2; i++)
#pragma unroll
        for (int j = 0; j < 4; j++) acc[i][j] = 0.f;

    for (int cc = 0; cc < CC1; cc += 32) {
        for (int i = t; i < 3 * 66 * 32; i += 256) {
            int c  = i & 31;
            int px = (i >> 5) % 66;
            int r  = i / (32 * 66);
            int yy = y - 1 + r;
            int xx = px - 1;
            float v = 0.f;
            if (yy >= 0 && yy < HH && xx >= 0 && xx < WW)
                v = g_xT[((b*HH + yy)*WW + xx) * CC1 + cc + c];
            s_in[(r * 66 + px) * 33 + c] = v;
        }
        for (int i = t; i < 9 * 32 * 32; i += 256) {
            int oc = i & 31;
            int c  = (i >> 5) & 31;
            int k  = i >> 10;
            float v = 0.f;
            if (oc < 18)       v = ow[oc * RED + (cc + c) * 9 + k];
            else if (oc < 27)  v = mw[(oc - 18) * RED + (cc + c) * 9 + k];
            s_w[(k * 32 + c) * 32 + oc] = v;
        }
        __syncthreads();

#pragma unroll
        for (int k = 0; k < 9; ++k) {
            int r = k / 3, dxm = k % 3;
            const float* si = &s_in[(r * 66 + px0 + dxm) * 33];
            const float* sw = &s_w[k * 32 * 32];
#pragma unroll 4
            for (int c = 0; c < 32; ++c) {
                float v0 = si[c];
                float v1 = si[33 + c];
#pragma unroll
                for (int j = 0; j < 4; ++j) {
                    float wv = sw[c * 32 + warp + 8 * j];
                    acc[0][j] += v0 * wv;
                    acc[1][j] += v1 * wv;
                }
            }
        }
        __syncthreads();
    }

#pragma unroll
    for (int pi = 0; pi < 2; ++pi) {
        int x = px0 + pi;
        int pix = (b*HH + y)*WW + x;
#pragma unroll
        for (int j = 0; j < 4; ++j) {
            int oc = warp + 8 * j;
            if (oc >= 27) continue;
            float v = acc[pi][j];
            if (oc < 18) {
                v += ob[oc];
                v = fminf(fmaxf(v, -16.0f), 16.0f);
                g_off[pix * 18 + oc] = v;
            } else {
                v += mb[oc - 18];
                g_mask[pix * 9 + (oc - 18)] = 1.0f / (1.0f + expf(-v));
            }
        }
    }
}

// ---------------------------------------------------------------------------
// Kernel 2: deformable gather + register-tiled GEMM.
// Block = (b, y, half-row): 32 px x 256 oc. 256 threads, 3 CTAs/SM.
//   thread t: ocg = t&63 (4 oc), pxg = t>>6 (8 px) -> 4x8 register tile.
// Per chunk (32 channels):
//   sampler: lane = channel, tasks = (k, px-quad); writes float4 with
//            XOR(ck&7) slot swizzle (conflict-bounded STS, coalesced gathers).
//   GEMM: ck unrolled x8 so swz = j is compile-time -> LDS offsets are
//         loop-invariant immediates and the 8 weight LDG.128s batch (MLP=8).
//   per ck: 1 LDG.128 (4 w) + 2 broadcast LDS.128 (8 px) + 16 FFMA2.
// ---------------------------------------------------------------------------
#define FMA2(d, a, b2) asm("fma.rn.f32x2 %0, %1, %2, %0;" : "+l"(d) : "l"(a), "l"(b2))

extern __shared__ float smem_dyn[];

__global__ void __launch_bounds__(256, 3) deform_kernel(float* __restrict__ out) {
    int blk = blockIdx.x;            // 0..1023
    int b   = blk >> 7;
    int y   = (blk >> 1) & 63;
    int x0  = (blk & 1) * PXB;

    float*  s_val = smem_dyn;                            // [288][32] floats, 36 KB
    int4*   s_idx = (int4*)(smem_dyn + CKL * PXB);       // [288]
    float4* s_wt  = (float4*)((char*)s_idx + KKT * PXB * sizeof(int4)); // [288]

    int t = threadIdx.x;
    int lane = t & 31, warp = t >> 5;

    // ---- coord phase: 288 entries (k, px) across half row ----
    for (int i = t; i < KKT * PXB; i += 256) {
        int k  = i >> 5;      // 0..8
        int xl = i & 31;
        int x  = x0 + xl;
        int pix = (b*HH + y)*WW + x;
        float dy = g_off[pix * 18 + 2 * k];
        float dx = g_off[pix * 18 + 2 * k + 1];
        float m  = g_mask[pix * 9 + k];
        float py  = dy + (float)(k / 3) + (float)(y - 1);
        float pxf = dx + (float)(k % 3) + (float)(x - 1);
        float y0f = floorf(py), x0f = floorf(pxf);
        float ly = py - y0f, lx = pxf - x0f;
        float hy = 1.f - ly, hx = 1.f - lx;
        int yi0 = (int)y0f, xi0 = (int)x0f;
        int yi1 = yi0 + 1, xi1 = xi0 + 1;
        bool vy0 = ((unsigned)yi0 < (unsigned)HH), vy1 = ((unsigned)yi1 < (unsigned)HH);
        bool vx0 = ((unsigned)xi0 < (unsigned)WW), vx1 = ((unsigned)xi1 < (unsigned)WW);
        int cy0 = min(max(yi0, 0), HH - 1), cy1 = min(max(yi1, 0), HH - 1);
        int cx0 = min(max(xi0, 0), WW - 1), cx1 = min(max(xi1, 0), WW - 1);
        int base = b * HWS;
        s_idx[i] = make_int4((base + cy0 * WW + cx0) * CC1,
                             (base + cy0 * WW + cx1) * CC1,
                             (base + cy1 * WW + cx0) * CC1,
                             (base + cy1 * WW + cx1) * CC1);
        s_wt[i] = make_float4(hy * hx * m * ((vy0 && vx0) ? 1.f : 0.f),
                              hy * lx * m * ((vy0 && vx1) ? 1.f : 0.f),
                              ly * hx * m * ((vy1 && vx0) ? 1.f : 0.f),
                              ly * lx * m * ((vy1 && vx1) ? 1.f : 0.f));
    }
    __syncthreads();

    int ocg  = t & 63;     // 4 consecutive oc starting at ocg*4
    int pxg  = t >> 6;     // 8 px starting at pxg*8
    int pxg2 = pxg * 2;    // logical float4-slot base (2 slots per thread)

    unsigned long long acc[4][4];
#pragma unroll
    for (int o = 0; o < 4; ++o)
#pragma unroll
        for (int i = 0; i < 4; ++i) acc[o][i] = 0ull;

    const float* __restrict__ xT = g_xT;
    const float4* __restrict__ wt4 = (const float4*)g_wT;  // [ck][64 float4]
    const ulonglong2* __restrict__ sv2 = (const ulonglong2*)s_val;
    float4* sv4 = (float4*)s_val;

    for (int cc = 0; cc < NCH; ++cc) {
        // ---- sampling: 72 tasks (k, px-quad), lane = channel ----
        int cb = cc * CCH + lane;
        for (int p = warp; p < KKT * 8; p += 8) {
            int k   = p >> 3;
            int px4 = p & 7;
            float vr[4];
#pragma unroll
            for (int j = 0; j < 4; ++j) {
                int e = k * PXB + px4 * 4 + j;
                int4   id = s_idx[e];
                float4 w  = s_wt[e];
                vr[j] = w.x * __ldg(&xT[id.x + cb])
                      + w.y * __ldg(&xT[id.y + cb])
                      + w.z * __ldg(&xT[id.z + cb])
                      + w.w * __ldg(&xT[id.w + cb]);
            }
            int ckl = lane * KKT + k;                     // c*9 + k
            sv4[ckl * 8 + (px4 ^ (ckl & 7))] = make_float4(vr[0], vr[1], vr[2], vr[3]);
        }
        __syncthreads();

        // ---- GEMM: thread = 4 oc x 8 px; ck unrolled x8 (swz=j const) ----
        const float4* __restrict__ wrow = wt4 + (size_t)(cc * CKL) * 64 + ocg;
#pragma unroll 1
        for (int ck8 = 0; ck8 < CKL / 8; ++ck8) {
#pragma unroll
            for (int j = 0; j < 8; ++j) {
                int ckl = ck8 * 8 + j;
                float4 w = __ldg(wrow + ckl * 64);
                ulonglong2 v0 = sv2[ckl * 8 + ((pxg2    ) ^ j)];
                ulonglong2 v1 = sv2[ckl * 8 + ((pxg2 + 1) ^ j)];
                unsigned long long w2;
#define DOOC(o, comp)                                                  \
                { unsigned wu = __float_as_uint(comp);                 \
                  asm("mov.b64 %0, {%1, %1};" : "=l"(w2) : "r"(wu));   \
                  FMA2(acc[o][0], v0.x, w2); FMA2(acc[o][1], v0.y, w2);\
                  FMA2(acc[o][2], v1.x, w2); FMA2(acc[o][3], v1.y, w2); }
                DOOC(0, w.x)
                DOOC(1, w.y)
                DOOC(2, w.z)
                DOOC(3, w.w)
#undef DOOC
            }
        }
        __syncthreads();
    }

    // ---- write NCHW output: 4 oc x 8 px per thread ----
    int xo = x0 + pxg * 8;
#pragma unroll
    for (int o = 0; o < 4; ++o) {
        int oc = ocg * 4 + o;
        float* op = out + (((size_t)(b * CC2 + oc) * HH + y) * WW + xo);
#pragma unroll
        for (int i = 0; i < 2; ++i) {
            unsigned long long a0 = acc[o][2 * i], a1 = acc[o][2 * i + 1];
            float4 o4;
            o4.x = __uint_as_float((unsigned)(a0 & 0xffffffffull));
            o4.y = __uint_as_float((unsigned)(a0 >> 32));
            o4.z = __uint_as_float((unsigned)(a1 & 0xffffffffull));
            o4.w = __uint_as_float((unsigned)(a1 >> 32));
            reinterpret_cast<float4*>(op)[i] = o4;
        }
    }
}

// ---------------------------------------------------------------------------
extern "C" void kernel_launch(void* const* d_in, const int* in_sizes, int n_in,
                              void* d_out, int out_size) {
    const float* x        = (const float*)d_in[0];
    const float* offset_w = (const float*)d_in[1];
    const float* offset_b = (const float*)d_in[2];
    const float* mod_w    = (const float*)d_in[3];
    const float* mod_b    = (const float*)d_in[4];
    const float* reg_w    = (const float*)d_in[5];
    float* out = (float*)d_out;

    const int DEFORM_SMEM = CKL * PXB * sizeof(float)           // s_val 36 KB
                          + KKT * PXB * sizeof(int4)            // s_idx 4.5 KB
                          + KKT * PXB * sizeof(float4);         // s_wt  4.5 KB
    cudaFuncSetAttribute(deform_kernel, cudaFuncAttributeMaxDynamicSharedMemorySize,
                         DEFORM_SMEM);

    dim3 tb(32, 8);
    dim3 tg(HWS / 32, CC1 / 32, BB);
    transpose_kernel<<<tg, tb>>>(x);
    wprep_kernel<<<RED, 256>>>(reg_w);
    conv1_kernel<<<BB * HH, 256>>>(offset_w, offset_b, mod_w, mod_b);
    deform_kernel<<<BB * HH * 2, 256, DEFORM_SMEM>>>(out);
}

// round 15
// speedup vs baseline: 1.8379x; 1.3123x over previous
#include <cuda_runtime.h>
#include <cuda_bf16.h>
#include <math.h>
#include <stdint.h>

// Problem constants
#define BB 8
#define CC1 256
#define CC2 256
#define HH 64
#define WW 64
#define HWS (HH*WW)           // 4096
#define KKT 9                 // taps
#define RED (CC1*KKT)         // 2304
#define NPX 64                // px per CTA (one row)
#define KC 64                 // K per chunk
#define NCHUNK 36             // 9 taps * 4 channel-blocks

// smem layout (dynamic)
#define A_STAGE   65536                    // per-stage A bytes (256 oc x 64 k x 2B x {hi,lo})
#define B_OFF     (2*A_STAGE)              // 131072
#define B_PASS_W  2080                     // words per pass: 4 ks * 520 (512 + 8 pad)
#define B_STAGE_B (2*B_PASS_W*4)           // 16640 B per stage (hi+lo)
#define DSMEM     (B_OFF + 2*B_STAGE_B)    // 164352 B

// Scratch (static device globals; allocation-free)
__device__ float g_xT[BB*HWS*CC1];     // NHWC x
__device__ float g_off[BB*HWS*18];     // per-pixel offsets (clipped)
__device__ float g_mask[BB*HWS*9];     // per-pixel sigmoid modulator
// weights in A-fragment order: [ch36][pass2][ks4][mtile16][lane32] uint4
__device__ uint4 g_wA[NCHUNK*2*4*16*32];

// ---------------------------------------------------------------------------
// Kernel T: NCHW -> NHWC transpose of x
// ---------------------------------------------------------------------------
__global__ void __launch_bounds__(256) transpose_kernel(const float* __restrict__ x) {
    __shared__ float tile[32][33];
    int b  = blockIdx.z;
    int c0 = blockIdx.y * 32;
    int s0 = blockIdx.x * 32;
    int tx = threadIdx.x, ty = threadIdx.y;
#pragma unroll
    for (int i = 0; i < 32; i += 8)
        tile[ty + i][tx] = x[((b*CC1) + (c0 + ty + i)) * HWS + s0 + tx];
    __syncthreads();
#pragma unroll
    for (int i = 0; i < 32; i += 8)
        g_xT[(b*HWS + s0 + ty + i) * CC1 + c0 + tx] = tile[tx][ty + i];
}

// ---------------------------------------------------------------------------
// Kernel W: reg_w [oc][c][tap] -> g_wA in exact m16n8k16 A-fragment order.
// block = (ch, pass, ks) flat; 512 threads: mtile = tid>>5, lane = tid&31.
// a_i: row = lane/4 + (i&1)*8, col = (lane%4)*2 + (i>>1)*8 (+half)
// ---------------------------------------------------------------------------
__global__ void __launch_bounds__(512) wprep_kernel(const float* __restrict__ rw) {
    int blk = blockIdx.x;               // = (ch*2 + p)*4 + ks
    int ks  = blk & 3;
    int p   = (blk >> 2) & 1;
    int ch  = blk >> 3;
    int tap = ch >> 2, cblock = ch & 3;
    int tid = threadIdx.x;
    int mt  = tid >> 5, lane = tid & 31;
    int r0  = lane >> 2, kk0 = (lane & 3) * 2;

    unsigned regs[4];
#pragma unroll
    for (int i = 0; i < 4; ++i) {
        int row = r0 + (i & 1) * 8;
        int col = kk0 + (i >> 1) * 8;
        int oc  = mt * 16 + row;
        unsigned hw[2];
#pragma unroll
        for (int h = 0; h < 2; ++h) {
            int c = cblock * 64 + ks * 16 + col + h;
            float v = rw[oc * RED + c * 9 + tap];
            __nv_bfloat16 hi = __float2bfloat16(v);
            __nv_bfloat16 ob;
            if (p == 0) ob = hi;
            else        ob = __float2bfloat16(v - __bfloat162float(hi));
            hw[h] = (unsigned)*reinterpret_cast<unsigned short*>(&ob);
        }
        regs[i] = hw[0] | (hw[1] << 16);
    }
    g_wA[(size_t)(blk * 16 + mt) * 32 + lane] = make_uint4(regs[0], regs[1], regs[2], regs[3]);
}

// ---------------------------------------------------------------------------
// Kernel 1: fused offset(18ch, clip +-16) + modulator(9ch, sigmoid) conv 3x3
// ---------------------------------------------------------------------------
__global__ void __launch_bounds__(256) conv1_kernel(const float* __restrict__ ow,
                                                    const float* __restrict__ ob,
                                                    const float* __restrict__ mw,
                                                    const float* __restrict__ mb) {
    int blk = blockIdx.x;
    int b = blk >> 6;
    int y = blk & 63;
    int t = threadIdx.x;
    int lane = t & 31, warp = t >> 5;
    int px0 = lane * 2;

    __shared__ float s_in[3 * 66 * 33];
    __shared__ float s_w[9 * 32 * 32];

    float acc[2][4];
#pragma unroll
    for (int i = 0; i < 2; i++)
#pragma unroll
        for (int j = 0; j < 4; j++) acc[i][j] = 0.f;

    for (int cc = 0; cc < CC1; cc += 32) {
        for (int i = t; i < 3 * 66 * 32; i += 256) {
            int c  = i & 31;
            int px = (i >> 5) % 66;
            int r  = i / (32 * 66);
            int yy = y - 1 + r;
            int xx = px - 1;
            float v = 0.f;
            if (yy >= 0 && yy < HH && xx >= 0 && xx < WW)
                v = g_xT[((b*HH + yy)*WW + xx) * CC1 + cc + c];
            s_in[(r * 66 + px) * 33 + c] = v;
        }
        for (int i = t; i < 9 * 32 * 32; i += 256) {
            int oc = i & 31;
            int c  = (i >> 5) & 31;
            int k  = i >> 10;
            float v = 0.f;
            if (oc < 18)       v = ow[oc * RED + (cc + c) * 9 + k];
            else if (oc < 27)  v = mw[(oc - 18) * RED + (cc + c) * 9 + k];
            s_w[(k * 32 + c) * 32 + oc] = v;
        }
        __syncthreads();

#pragma unroll
        for (int k = 0; k < 9; ++k) {
            int r = k / 3, dxm = k % 3;
            const float* si = &s_in[(r * 66 + px0 + dxm) * 33];
            const float* sw = &s_w[k * 32 * 32];
#pragma unroll 4
            for (int c = 0; c < 32; ++c) {
                float v0 = si[c];
                float v1 = si[33 + c];
#pragma unroll
                for (int j = 0; j < 4; ++j) {
                    float wv = sw[c * 32 + warp + 8 * j];
                    acc[0][j] += v0 * wv;
                    acc[1][j] += v1 * wv;
                }
            }
        }
        __syncthreads();
    }

#pragma unroll
    for (int pi = 0; pi < 2; ++pi) {
        int x = px0 + pi;
        int pix = (b*HH + y)*WW + x;
#pragma unroll
        for (int j = 0; j < 4; ++j) {
            int oc = warp + 8 * j;
            if (oc >= 27) continue;
            float v = acc[pi][j];
            if (oc < 18) {
                v += ob[oc];
                v = fminf(fmaxf(v, -16.0f), 16.0f);
                g_off[pix * 18 + oc] = v;
            } else {
                v += mb[oc - 18];
                g_mask[pix * 9 + (oc - 18)] = 1.0f / (1.0f + expf(-v));
            }
        }
    }
}

// ---------------------------------------------------------------------------
// Kernel 2: deformable gather + mma.sync bf16-split GEMM (fallback HMMA).
// CTA = (b, y): D[256 oc x 64 px], K=2304 in 36 chunks of 64.
// 8 warps (256 thr): warp = 4(m) x 2(n) grid; per-warp tile 64oc x 32px.
// Per chunk: sampler writes B-frags (bf16 hi/lo) into padded smem; A chunk
// (pre-fragmented in gmem) copied 64KB coalesced. Double-buffered, one
// barrier per chunk; consume(k-1) before produce(k) for cross-warp overlap.
// 3 passes: Ahi*Bhi + Ahi*Blo + Alo*Bhi, fp32 register accumulators.
// ---------------------------------------------------------------------------
#define MMA16816(C, A, B)                                                      \
    asm volatile("mma.sync.aligned.m16n8k16.row.col.f32.bf16.bf16.f32 "        \
        "{%0,%1,%2,%3}, {%4,%5,%6,%7}, {%8,%9}, {%0,%1,%2,%3};"                \
        : "+f"(C[0]), "+f"(C[1]), "+f"(C[2]), "+f"(C[3])                       \
        : "r"(A.x), "r"(A.y), "r"(A.z), "r"(A.w), "r"(B.x), "r"(B.y))

extern __shared__ char smem_dyn[];

__global__ void __launch_bounds__(256) deform_kernel(float* __restrict__ out) {
    int b = blockIdx.x >> 6;
    int y = blockIdx.x & 63;
    int tid = threadIdx.x;
    int w = tid >> 5, lane = tid & 31;
    int wm = w >> 1, wn = w & 1;

    __shared__ int4   s_idx[NPX];
    __shared__ float4 s_wt[NPX];

    float acc[4][4][4];
#pragma unroll
    for (int mt = 0; mt < 4; ++mt)
#pragma unroll
        for (int nt = 0; nt < 4; ++nt)
#pragma unroll
            for (int i = 0; i < 4; ++i) acc[mt][nt][i] = 0.f;

    const float* __restrict__ xT = g_xT;

    for (int it = 0; it <= NCHUNK; ++it) {
        // ---- coords for a new tap (uniform branch) ----
        if (it < NCHUNK && (it & 3) == 0) {
            int tap = it >> 2;
            if (tid < NPX) {
                int x = tid;
                int pix = (b*HH + y)*WW + x;
                float dyo = g_off[pix * 18 + 2 * tap];
                float dxo = g_off[pix * 18 + 2 * tap + 1];
                float m   = g_mask[pix * 9 + tap];
                float py  = dyo + (float)(tap / 3) + (float)(y - 1);
                float pxf = dxo + (float)(tap % 3) + (float)(x - 1);
                float y0f = floorf(py), x0f = floorf(pxf);
                float ly = py - y0f, lx = pxf - x0f;
                float hy = 1.f - ly, hx = 1.f - lx;
                int yi0 = (int)y0f, xi0 = (int)x0f;
                int yi1 = yi0 + 1, xi1 = xi0 + 1;
                bool vy0 = ((unsigned)yi0 < (unsigned)HH), vy1 = ((unsigned)yi1 < (unsigned)HH);
                bool vx0 = ((unsigned)xi0 < (unsigned)WW), vx1 = ((unsigned)xi1 < (unsigned)WW);
                int cy0 = min(max(yi0, 0), HH - 1), cy1 = min(max(yi1, 0), HH - 1);
                int cx0 = min(max(xi0, 0), WW - 1), cx1 = min(max(xi1, 0), WW - 1);
                int base = b * HWS;
                s_idx[tid] = make_int4((base + cy0 * WW + cx0) * CC1,
                                       (base + cy0 * WW + cx1) * CC1,
                                       (base + cy1 * WW + cx0) * CC1,
                                       (base + cy1 * WW + cx1) * CC1);
                s_wt[tid] = make_float4(hy * hx * m * ((vy0 && vx0) ? 1.f : 0.f),
                                        hy * lx * m * ((vy0 && vx1) ? 1.f : 0.f),
                                        ly * hx * m * ((vy1 && vx0) ? 1.f : 0.f),
                                        ly * lx * m * ((vy1 && vx1) ? 1.f : 0.f));
            }
            __syncthreads();
        }

        // ---- consume chunk it-1 from stage (it-1)&1 ----
        if (it >= 1) {
            int ss = (it - 1) & 1;
            const uint4* __restrict__ Ab = (const uint4*)(smem_dyn + ss * A_STAGE);
            const unsigned* __restrict__ Bb = (const unsigned*)(smem_dyn + B_OFF + ss * B_STAGE_B);
#pragma unroll
            for (int ks = 0; ks < 4; ++ks) {
                uint4 ah[4], al[4];
#pragma unroll
                for (int mt = 0; mt < 4; ++mt) {
                    ah[mt] = Ab[(size_t)((0 + ks) * 16 + wm * 4 + mt) * 32 + lane];
                    al[mt] = Ab[(size_t)((4 + ks) * 16 + wm * 4 + mt) * 32 + lane];
                }
                uint2 bh[4], bl[4];
#pragma unroll
                for (int nt = 0; nt < 4; ++nt) {
                    int wbase = ks * 520 + ((wn * 4 + nt) * 32 + lane) * 2;
                    bh[nt] = *(const uint2*)(Bb + wbase);
                    bl[nt] = *(const uint2*)(Bb + B_PASS_W + wbase);
                }
#pragma unroll
                for (int mt = 0; mt < 4; ++mt)
#pragma unroll
                    for (int nt = 0; nt < 4; ++nt) {
                        MMA16816(acc[mt][nt], ah[mt], bh[nt]);
                        MMA16816(acc[mt][nt], ah[mt], bl[nt]);
                        MMA16816(acc[mt][nt], al[mt], bh[nt]);
                    }
            }
        }

        // ---- produce chunk it into stage it&1 ----
        if (it < NCHUNK) {
            int ch = it, s = it & 1, cblock = ch & 3;
            unsigned* Bh = (unsigned*)(smem_dyn + B_OFF + s * B_STAGE_B);
            unsigned* Bl = Bh + B_PASS_W;
            // sampler: lane = channel pair (2*lane, 2*lane+1), warp covers px w*8..w*8+7
            int c0 = cblock * 64 + 2 * lane;
            int wbase0 = (lane >> 3) * 520 + ((lane >> 2) & 1);
#pragma unroll
            for (int j = 0; j < 8; ++j) {
                int px = w * 8 + j;
                int4   id = s_idx[px];
                float4 wt = s_wt[px];
                float2 a0 = *(const float2*)(xT + id.x + c0);
                float2 a1 = *(const float2*)(xT + id.y + c0);
                float2 a2 = *(const float2*)(xT + id.z + c0);
                float2 a3 = *(const float2*)(xT + id.w + c0);
                float v0 = wt.x*a0.x + wt.y*a1.x + wt.z*a2.x + wt.w*a3.x;
                float v1 = wt.x*a0.y + wt.y*a1.y + wt.z*a2.y + wt.w*a3.y;
                unsigned hi, lo;
                asm("cvt.rn.bf16x2.f32 %0, %1, %2;" : "=r"(hi) : "f"(v1), "f"(v0));
                float h0 = __uint_as_float(hi << 16);
                float h1 = __uint_as_float(hi & 0xffff0000u);
                float l0 = v0 - h0, l1 = v1 - h1;
                asm("cvt.rn.bf16x2.f32 %0, %1, %2;" : "=r"(lo) : "f"(l1), "f"(l0));
                int wd = wbase0 + (w * 32 + j * 4 + (lane & 3)) * 2;
                Bh[wd] = hi;
                Bl[wd] = lo;
            }
            // A copy: 64KB coalesced, pre-fragmented in gmem
            const uint4* __restrict__ asrc = g_wA + (size_t)ch * 4096;
            uint4* adst = (uint4*)(smem_dyn + s * A_STAGE);
#pragma unroll
            for (int i = 0; i < 16; ++i)
                adst[tid + i * 256] = __ldg(asrc + tid + i * 256);
        }
        __syncthreads();
    }

    // ---- epilogue: fragment -> NCHW gmem ----
    // C frag: c0,c1 at (row, col..col+1); c2,c3 at (row+8, ...). row is the
    // M (=oc) axis, so the +8 step is 8 CHANNELS => stride 8*HWS (not 8*WW).
    int r0 = lane >> 2, cc0 = (lane & 3) * 2;
#pragma unroll
    for (int mt = 0; mt < 4; ++mt) {
        int oc = wm * 64 + mt * 16 + r0;
#pragma unroll
        for (int nt = 0; nt < 4; ++nt) {
            int px = wn * 32 + nt * 8 + cc0;
            float* op = out + (((size_t)(b * CC2 + oc) * HH + y) * WW + px);
            *(float2*)op = make_float2(acc[mt][nt][0], acc[mt][nt][1]);
            *(float2*)(op + (size_t)8 * HWS) = make_float2(acc[mt][nt][2], acc[mt][nt][3]);
        }
    }
}

// ---------------------------------------------------------------------------
extern "C" void kernel_launch(void* const* d_in, const int* in_sizes, int n_in,
                              void* d_out, int out_size) {
    const float* x        = (const float*)d_in[0];
    const float* offset_w = (const float*)d_in[1];
    const float* offset_b = (const float*)d_in[2];
    const float* mod_w    = (const float*)d_in[3];
    const float* mod_b    = (const float*)d_in[4];
    const float* reg_w    = (const float*)d_in[5];
    float* out = (float*)d_out;

    cudaFuncSetAttribute(deform_kernel, cudaFuncAttributeMaxDynamicSharedMemorySize, DSMEM);

    dim3 tb(32, 8);
    dim3 tg(HWS / 32, CC1 / 32, BB);
    transpose_kernel<<<tg, tb>>>(x);
    wprep_kernel<<<NCHUNK * 8, 512>>>(reg_w);
    conv1_kernel<<<BB * HH, 256>>>(offset_w, offset_b, mod_w, mod_b);
    deform_kernel<<<BB * HH, 256, DSMEM>>>(out);
}

// round 16
// speedup vs baseline: 2.1650x; 1.1780x over previous
#include <cuda_runtime.h>
#include <cuda_bf16.h>
#include <math.h>
#include <stdint.h>

// Problem constants
#define BB 8
#define CC1 256
#define CC2 256
#define HH 64
#define WW 64
#define HWS (HH*WW)           // 4096
#define KKT 9                 // taps
#define RED (CC1*KKT)         // 2304
#define NPX 128               // px per CTA (two rows)
#define KC 64                 // K per chunk
#define NCHUNK 36             // 9 taps * 4 channel-blocks

// smem layout (dynamic)
#define A_STAGE   65536                    // per-stage A bytes (256 oc x 64 k x 2B x {hi,lo})
#define B_OFF     (2*A_STAGE)              // 131072
#define KS_W      1032                     // words per ks block: 1024 + 8 pad (8 mod 32 keeps STS conflict-free)
#define B_PASS_W  (4*KS_W)                 // 4128 words per pass
#define B_STAGE_B (2*B_PASS_W*4)           // 33024 B per stage (hi+lo)
#define DSMEM     (B_OFF + 2*B_STAGE_B)    // 197120 B

// Scratch (static device globals; allocation-free)
__device__ float g_xT[BB*HWS*CC1];     // NHWC x
__device__ float g_off[BB*HWS*18];     // per-pixel offsets (clipped)
__device__ float g_mask[BB*HWS*9];     // per-pixel sigmoid modulator
// weights in A-fragment order: [ch36][pass2][ks4][mtile16][lane32] uint4
__device__ uint4 g_wA[NCHUNK*2*4*16*32];

// ---------------------------------------------------------------------------
// Kernel T: NCHW -> NHWC transpose of x
// ---------------------------------------------------------------------------
__global__ void __launch_bounds__(256) transpose_kernel(const float* __restrict__ x) {
    __shared__ float tile[32][33];
    int b  = blockIdx.z;
    int c0 = blockIdx.y * 32;
    int s0 = blockIdx.x * 32;
    int tx = threadIdx.x, ty = threadIdx.y;
#pragma unroll
    for (int i = 0; i < 32; i += 8)
        tile[ty + i][tx] = x[((b*CC1) + (c0 + ty + i)) * HWS + s0 + tx];
    __syncthreads();
#pragma unroll
    for (int i = 0; i < 32; i += 8)
        g_xT[(b*HWS + s0 + ty + i) * CC1 + c0 + tx] = tile[tx][ty + i];
}

// ---------------------------------------------------------------------------
// Kernel W: reg_w [oc][c][tap] -> g_wA in exact m16n8k16 A-fragment order.
// ---------------------------------------------------------------------------
__global__ void __launch_bounds__(512) wprep_kernel(const float* __restrict__ rw) {
    int blk = blockIdx.x;               // = (ch*2 + p)*4 + ks
    int ks  = blk & 3;
    int p   = (blk >> 2) & 1;
    int ch  = blk >> 3;
    int tap = ch >> 2, cblock = ch & 3;
    int tid = threadIdx.x;
    int mt  = tid >> 5, lane = tid & 31;
    int r0  = lane >> 2, kk0 = (lane & 3) * 2;

    unsigned regs[4];
#pragma unroll
    for (int i = 0; i < 4; ++i) {
        int row = r0 + (i & 1) * 8;
        int col = kk0 + (i >> 1) * 8;
        int oc  = mt * 16 + row;
        unsigned hw[2];
#pragma unroll
        for (int h = 0; h < 2; ++h) {
            int c = cblock * 64 + ks * 16 + col + h;
            float v = rw[oc * RED + c * 9 + tap];
            __nv_bfloat16 hi = __float2bfloat16(v);
            __nv_bfloat16 ob;
            if (p == 0) ob = hi;
            else        ob = __float2bfloat16(v - __bfloat162float(hi));
            hw[h] = (unsigned)*reinterpret_cast<unsigned short*>(&ob);
        }
        regs[i] = hw[0] | (hw[1] << 16);
    }
    g_wA[(size_t)(blk * 16 + mt) * 32 + lane] = make_uint4(regs[0], regs[1], regs[2], regs[3]);
}

// ---------------------------------------------------------------------------
// Kernel 1: fused offset(18ch, clip +-16) + modulator(9ch, sigmoid) conv 3x3
// ---------------------------------------------------------------------------
__global__ void __launch_bounds__(256) conv1_kernel(const float* __restrict__ ow,
                                                    const float* __restrict__ ob,
                                                    const float* __restrict__ mw,
                                                    const float* __restrict__ mb) {
    int blk = blockIdx.x;
    int b = blk >> 6;
    int y = blk & 63;
    int t = threadIdx.x;
    int lane = t & 31, warp = t >> 5;
    int px0 = lane * 2;

    __shared__ float s_in[3 * 66 * 33];
    __shared__ float s_w[9 * 32 * 32];

    float acc[2][4];
#pragma unroll
    for (int i = 0; i < 2; i++)
#pragma unroll
        for (int j = 0; j < 4; j++) acc[i][j] = 0.f;

    for (int cc = 0; cc < CC1; cc += 32) {
        for (int i = t; i < 3 * 66 * 32; i += 256) {
            int c  = i & 31;
            int px = (i >> 5) % 66;
            int r  = i / (32 * 66);
            int yy = y - 1 + r;
            int xx = px - 1;
            float v = 0.f;
            if (yy >= 0 && yy < HH && xx >= 0 && xx < WW)
                v = g_xT[((b*HH + yy)*WW + xx) * CC1 + cc + c];
            s_in[(r * 66 + px) * 33 + c] = v;
        }
        for (int i = t; i < 9 * 32 * 32; i += 256) {
            int oc = i & 31;
            int c  = (i >> 5) & 31;
            int k  = i >> 10;
            float v = 0.f;
            if (oc < 18)       v = ow[oc * RED + (cc + c) * 9 + k];
            else if (oc < 27)  v = mw[(oc - 18) * RED + (cc + c) * 9 + k];
            s_w[(k * 32 + c) * 32 + oc] = v;
        }
        __syncthreads();

#pragma unroll
        for (int k = 0; k < 9; ++k) {
            int r = k / 3, dxm = k % 3;
            const float* si = &s_in[(r * 66 + px0 + dxm) * 33];
            const float* sw = &s_w[k * 32 * 32];
#pragma unroll 4
            for (int c = 0; c < 32; ++c) {
                float v0 = si[c];
                float v1 = si[33 + c];
#pragma unroll
                for (int j = 0; j < 4; ++j) {
                    float wv = sw[c * 32 + warp + 8 * j];
                    acc[0][j] += v0 * wv;
                    acc[1][j] += v1 * wv;
                }
            }
        }
        __syncthreads();
    }

#pragma unroll
    for (int pi = 0; pi < 2; ++pi) {
        int x = px0 + pi;
        int pix = (b*HH + y)*WW + x;
#pragma unroll
        for (int j = 0; j < 4; ++j) {
            int oc = warp + 8 * j;
            if (oc >= 27) continue;
            float v = acc[pi][j];
            if (oc < 18) {
                v += ob[oc];
                v = fminf(fmaxf(v, -16.0f), 16.0f);
                g_off[pix * 18 + oc] = v;
            } else {
                v += mb[oc - 18];
                g_mask[pix * 9 + (oc - 18)] = 1.0f / (1.0f + expf(-v));
            }
        }
    }
}

// ---------------------------------------------------------------------------
// Kernel 2: deformable gather + mma.sync bf16-split GEMM (fallback HMMA).
// CTA = (b, row-pair): D[256 oc x 128 px], K=2304 in 36 chunks of 64.
// 16 warps (512 thr): warp = 4(m) x 4(n); per-warp tile 64oc x 32px.
// Per chunk: A copied via cp.async (issued first, waited after sampling);
// sampler writes B-frags (bf16 hi/lo) into padded smem. Double-buffered,
// one barrier per chunk; consume(k-1) before produce(k).
// 3 passes: Ahi*Bhi + Ahi*Blo + Alo*Bhi, fp32 register accumulators.
// ---------------------------------------------------------------------------
#define MMA16816(C, A, B)                                                      \
    asm volatile("mma.sync.aligned.m16n8k16.row.col.f32.bf16.bf16.f32 "        \
        "{%0,%1,%2,%3}, {%4,%5,%6,%7}, {%8,%9}, {%0,%1,%2,%3};"                \
        : "+f"(C[0]), "+f"(C[1]), "+f"(C[2]), "+f"(C[3])                       \
        : "r"(A.x), "r"(A.y), "r"(A.z), "r"(A.w), "r"(B.x), "r"(B.y))

extern __shared__ char smem_dyn[];

__global__ void __launch_bounds__(512, 1) deform_kernel(float* __restrict__ out) {
    int b  = blockIdx.x >> 5;
    int y0 = (blockIdx.x & 31) * 2;
    int tid = threadIdx.x;
    int w = tid >> 5, lane = tid & 31;
    int wm = w >> 2, wn = w & 3;

    __shared__ int4   s_idx[NPX];
    __shared__ float4 s_wt[NPX];

    float acc[4][4][4];
#pragma unroll
    for (int mt = 0; mt < 4; ++mt)
#pragma unroll
        for (int nt = 0; nt < 4; ++nt)
#pragma unroll
            for (int i = 0; i < 4; ++i) acc[mt][nt][i] = 0.f;

    const float* __restrict__ xT = g_xT;

    for (int it = 0; it <= NCHUNK; ++it) {
        // ---- coords for a new tap (uniform branch) ----
        if (it < NCHUNK && (it & 3) == 0) {
            int tap = it >> 2;
            if (tid < NPX) {
                int x  = tid & 63;
                int yy = y0 + (tid >> 6);
                int pix = (b*HH + yy)*WW + x;
                float dyo = g_off[pix * 18 + 2 * tap];
                float dxo = g_off[pix * 18 + 2 * tap + 1];
                float m   = g_mask[pix * 9 + tap];
                float py  = dyo + (float)(tap / 3) + (float)(yy - 1);
                float pxf = dxo + (float)(tap % 3) + (float)(x - 1);
                float y0f = floorf(py), x0f = floorf(pxf);
                float ly = py - y0f, lx = pxf - x0f;
                float hy = 1.f - ly, hx = 1.f - lx;
                int yi0 = (int)y0f, xi0 = (int)x0f;
                int yi1 = yi0 + 1, xi1 = xi0 + 1;
                bool vy0 = ((unsigned)yi0 < (unsigned)HH), vy1 = ((unsigned)yi1 < (unsigned)HH);
                bool vx0 = ((unsigned)xi0 < (unsigned)WW), vx1 = ((unsigned)xi1 < (unsigned)WW);
                int cy0 = min(max(yi0, 0), HH - 1), cy1 = min(max(yi1, 0), HH - 1);
                int cx0 = min(max(xi0, 0), WW - 1), cx1 = min(max(xi1, 0), WW - 1);
                int base = b * HWS;
                s_idx[tid] = make_int4((base + cy0 * WW + cx0) * CC1,
                                       (base + cy0 * WW + cx1) * CC1,
                                       (base + cy1 * WW + cx0) * CC1,
                                       (base + cy1 * WW + cx1) * CC1);
                s_wt[tid] = make_float4(hy * hx * m * ((vy0 && vx0) ? 1.f : 0.f),
                                        hy * lx * m * ((vy0 && vx1) ? 1.f : 0.f),
                                        ly * hx * m * ((vy1 && vx0) ? 1.f : 0.f),
                                        ly * lx * m * ((vy1 && vx1) ? 1.f : 0.f));
            }
            __syncthreads();
        }

        // ---- consume chunk it-1 from stage (it-1)&1 ----
        if (it >= 1) {
            int ss = (it - 1) & 1;
            const uint4* __restrict__ Ab = (const uint4*)(smem_dyn + ss * A_STAGE);
            const unsigned* __restrict__ Bb = (const unsigned*)(smem_dyn + B_OFF + ss * B_STAGE_B);
#pragma unroll
            for (int ks = 0; ks < 4; ++ks) {
                uint4 ah[4], al[4];
#pragma unroll
                for (int mt = 0; mt < 4; ++mt) {
                    ah[mt] = Ab[(size_t)((0 + ks) * 16 + wm * 4 + mt) * 32 + lane];
                    al[mt] = Ab[(size_t)((4 + ks) * 16 + wm * 4 + mt) * 32 + lane];
                }
                uint2 bh[4], bl[4];
#pragma unroll
                for (int nt = 0; nt < 4; ++nt) {
                    int wbase = ks * KS_W + ((wn * 4 + nt) * 32 + lane) * 2;
                    bh[nt] = *(const uint2*)(Bb + wbase);
                    bl[nt] = *(const uint2*)(Bb + B_PASS_W + wbase);
                }
#pragma unroll
                for (int mt = 0; mt < 4; ++mt)
#pragma unroll
                    for (int nt = 0; nt < 4; ++nt) {
                        MMA16816(acc[mt][nt], ah[mt], bh[nt]);
                        MMA16816(acc[mt][nt], ah[mt], bl[nt]);
                        MMA16816(acc[mt][nt], al[mt], bh[nt]);
                    }
            }
        }

        // ---- produce chunk it into stage it&1 ----
        if (it < NCHUNK) {
            int ch = it, s = it & 1, cblock = ch & 3;
            // 1) kick off A copy (cp.async, 64KB): latency hides under sampling
            {
                unsigned adst = (unsigned)__cvta_generic_to_shared(smem_dyn + s * A_STAGE) + tid * 16;
                const char* asrc = (const char*)(g_wA + (size_t)ch * 4096) + tid * 16;
#pragma unroll
                for (int i = 0; i < 8; ++i)
                    asm volatile("cp.async.cg.shared.global [%0], [%1], 16;"
                                 :: "r"(adst + i * 8192), "l"(asrc + i * 8192));
                asm volatile("cp.async.commit_group;" ::: "memory");
            }
            // 2) sampler: lane = channel pair, warp w covers px w*8..w*8+7
            unsigned* Bh = (unsigned*)(smem_dyn + B_OFF + s * B_STAGE_B);
            unsigned* Bl = Bh + B_PASS_W;
            int c0 = cblock * 64 + 2 * lane;
            int wbase0 = (lane >> 3) * KS_W + ((lane >> 2) & 1) + (lane & 3) * 2 + w * 64;
#pragma unroll
            for (int j = 0; j < 8; ++j) {
                int px = w * 8 + j;
                int4   id = s_idx[px];
                float4 wt = s_wt[px];
                float2 a0 = *(const float2*)(xT + id.x + c0);
                float2 a1 = *(const float2*)(xT + id.y + c0);
                float2 a2 = *(const float2*)(xT + id.z + c0);
                float2 a3 = *(const float2*)(xT + id.w + c0);
                float v0 = wt.x*a0.x + wt.y*a1.x + wt.z*a2.x + wt.w*a3.x;
                float v1 = wt.x*a0.y + wt.y*a1.y + wt.z*a2.y + wt.w*a3.y;
                unsigned hi, lo;
                asm("cvt.rn.bf16x2.f32 %0, %1, %2;" : "=r"(hi) : "f"(v1), "f"(v0));
                float h0 = __uint_as_float(hi << 16);
                float h1 = __uint_as_float(hi & 0xffff0000u);
                float l0 = v0 - h0, l1 = v1 - h1;
                asm("cvt.rn.bf16x2.f32 %0, %1, %2;" : "=r"(lo) : "f"(l1), "f"(l0));
                int wd = wbase0 + j * 8;
                Bh[wd] = hi;
                Bl[wd] = lo;
            }
            // 3) drain A copy before the barrier publishes the stage
            asm volatile("cp.async.wait_group 0;" ::: "memory");
        }
        __syncthreads();
    }

    // ---- epilogue: fragment -> NCHW gmem ----
    // C frag: c0,c1 at (oc_row, px..px+1); c2,c3 at (oc_row+8, ...) => +8*HWS.
    int r0 = lane >> 2, cc0 = (lane & 3) * 2;
#pragma unroll
    for (int mt = 0; mt < 4; ++mt) {
        int oc = wm * 64 + mt * 16 + r0;
#pragma unroll
        for (int nt = 0; nt < 4; ++nt) {
            int ntg = wn * 4 + nt;                 // 0..15
            int yy  = y0 + (ntg >> 3);
            int px  = (ntg & 7) * 8 + cc0;
            float* op = out + (((size_t)(b * CC2 + oc) * HH + yy) * WW + px);
            *(float2*)op = make_float2(acc[mt][nt][0], acc[mt][nt][1]);
            *(float2*)(op + (size_t)8 * HWS) = make_float2(acc[mt][nt][2], acc[mt][nt][3]);
        }
    }
}

// ---------------------------------------------------------------------------
extern "C" void kernel_launch(void* const* d_in, const int* in_sizes, int n_in,
                              void* d_out, int out_size) {
    const float* x        = (const float*)d_in[0];
    const float* offset_w = (const float*)d_in[1];
    const float* offset_b = (const float*)d_in[2];
    const float* mod_w    = (const float*)d_in[3];
    const float* mod_b    = (const float*)d_in[4];
    const float* reg_w    = (const float*)d_in[5];
    float* out = (float*)d_out;

    cudaFuncSetAttribute(deform_kernel, cudaFuncAttributeMaxDynamicSharedMemorySize, DSMEM);

    dim3 tb(32, 8);
    dim3 tg(HWS / 32, CC1 / 32, BB);
    transpose_kernel<<<tg, tb>>>(x);
    wprep_kernel<<<NCHUNK * 8, 512>>>(reg_w);
    conv1_kernel<<<BB * HH, 256>>>(offset_w, offset_b, mod_w, mod_b);
    deform_kernel<<<BB * 32, 512, DSMEM>>>(out);
}